// round 10
// baseline (speedup 1.0000x reference)
#include <cuda_runtime.h>
#include <cstdint>

// ---------------- problem constants ----------------
#define HH   48
#define WW   160
#define BB   32
#define CIn  32
#define NG   160            // 5*CL
#define CO_  64
#define HOo  24
#define WOo  80
#define CELLSZ 1024         // B*CL per (row,col) cell
#define DIRSZ  (HH*WW*CELLSZ)
#define NPAIR 24            // HH/2
#define NCHAIN 8            // 4 dirs x 2 batch halves

// ---------------- device scratch (static: allocation-free) ----------------
__device__ float    g_xT[HH*WW*BB*CIn];      // [r][c][ci][b]  (k-major for staging)
__device__ float    g_hd[4*DIRSZ];           // [d][row][col][bh*512 + ch*16 + bhat]
__device__ float    g_cd[4*DIRSZ];           // same layout (boundary rows used)
__device__ unsigned g_prog[NCHAIN*NPAIR];    // per-(chain,pair) boundary progress
__device__ float    g_y [BB*CO_*HOo*WOo];    // pre-norm conv output
__device__ float    g_ps1[BB*HOo*CO_];
__device__ float    g_ps2[BB*HOo*CO_];
__device__ float    g_sc[CO_];
__device__ float    g_sh[CO_];

// ---------------- helpers ----------------
__device__ __forceinline__ unsigned ld_acq(const unsigned* p) {
    unsigned v;
    asm volatile("ld.acquire.gpu.global.u32 %0, [%1];" : "=r"(v) : "l"(p) : "memory");
    return v;
}
__device__ __forceinline__ void st_rel(unsigned* p, unsigned v) {
    asm volatile("st.release.gpu.global.u32 [%0], %1;" :: "l"(p), "r"(v) : "memory");
}
__device__ __forceinline__ float fsigmoid(float x) {
    float e = __expf(-x);
    return __fdividef(1.0f, 1.0f + e);
}
__device__ __forceinline__ float ftanh(float x) {
    float ax = fabsf(x);
    float e  = __expf(-2.0f * ax);          // in (0,1], never overflows
    float r  = __fdividef(1.0f - e, 1.0f + e);
    return copysignf(r, x);
}

// ---------------- kernel 0: transpose x (k-major) + reset progress ----------------
__global__ void prep_kernel(const float* __restrict__ x) {
    int t = blockIdx.x * blockDim.x + threadIdx.x;   // 7680*256 threads, 1 float4 each
    if (t < NCHAIN*NPAIR) g_prog[t] = 0;
    int i0 = t * 4;
    int b0 = i0 & 31;                 // batch (fastest)
    int ci = (i0 >> 5) & 31;
    int c  = (i0 >> 10) % WW;
    int r  = i0 / (WW * CELLSZ);
    const float* xp = x + (((size_t)(b0*CIn + ci))*HH + r)*WW + c;
    const size_t bs = (size_t)CIn*HH*WW;  // stride between batches
    float4 v;
    v.x = xp[0];
    v.y = xp[bs];
    v.z = xp[2*bs];
    v.w = xp[3*bs];
    *(float4*)(g_xT + i0) = v;
}

// noop kernels: shift ncu's capture window onto mdlstm_kernel
__global__ void noop_kernel() {}

// ---------------- kernel 1: 4-dir MDLSTM, paired rows, batch-split ----------------
// 192 CTAs x 128 threads; 2 CTAs co-resident per SM -> serial phases interleave.
// smem floats per CTA:
//   Ws[96*160]=15360 | Bs[160] | At[96*36]=3456 (k-major A: cols 0-15 cell0 bhat,
//   16-31 cell1 bhat) | Zs[32*164]=5248 | Cl[32*32] | Ct0[16*32]
#define AT_P 36
#define ZP   164
#define SM_WS  0
#define SM_BS  15360
#define SM_AT  15520
#define SM_ZS  18976
#define SM_CL  24224
#define SM_CT0 25248
#define SM_TOT 25760     // floats -> 103,040 bytes (x2 = 206 KB <= 227 KB)

__launch_bounds__(128)
__global__ void mdlstm_kernel(const float* __restrict__ Wx, const float* __restrict__ Ul,
                              const float* __restrict__ Ut, const float* __restrict__ bias) {
    extern __shared__ float sm[];
    float* Ws  = sm + SM_WS;    // [96][160]: k 0..31 Wx, 32..63 Ul, 64..95 Ut
    float* Bs  = sm + SM_BS;
    float* At  = sm + SM_AT;    // [96][36] k-major A panel
    float* Zs  = sm + SM_ZS;    // [32][164]
    float* Cl  = sm + SM_CL;    // c_left  [row32][ch32]
    float* Ct0 = sm + SM_CT0;   // c_top cell0 [bhat16][ch32]

    const int tid   = threadIdx.x;
    const int chain = blockIdx.x / NPAIR;      // d*2 + bh
    const int p     = blockIdx.x % NPAIR;
    const int d     = chain >> 1;
    const int bh    = chain & 1;
    const bool flipH = (d >= 2);
    const bool flipW = (d & 1);
    const int r0  = 2*p;
    const int r1  = 2*p + 1;
    const int r0o = flipH ? (HH-1-r0) : r0;
    const int r1o = flipH ? (HH-1-r1) : r1;

    for (int i = tid; i < 32*NG; i += 128) {
        Ws[i]         = Wx[d*32*NG + i];
        Ws[32*NG + i] = Ul[d*32*NG + i];
        Ws[64*NG + i] = Ut[d*32*NG + i];
    }
    for (int i = tid; i < NG; i += 128) Bs[i] = bias[d*NG + i];
    for (int i = tid; i < 96*AT_P; i += 128) At[i] = 0.0f;
    for (int i = tid; i < 1024; i += 128) {
        Cl[i] = 0.0f;
        if (i < 512) Ct0[i] = 0.0f;
    }
    __syncthreads();

    // GEMM map: 4 rows x 10 cols per thread
    const int rg = tid >> 4;             // 0..7  (rows rg*4 .. rg*4+3)
    const int cg = tid & 15;             // 10 contiguous output cols
    // gates map: channel gch, bhats bq..bq+3, BOTH cells handled by same thread
    const int gch = tid & 31;
    const int bq  = (tid >> 5) * 4;
    // staging map: 1 channel x 4 batches per thread (conflict-free STS.128)
    const int sci = tid & 31;
    const int sb0 = (tid >> 5) * 4;

    unsigned* myflag = &g_prog[chain*NPAIR + p];
    const unsigned* upflag = (p > 0) ? &g_prog[chain*NPAIR + p - 1] : 0;

    // bias slice in registers (f32x2 pairs)
    unsigned long long breg[5];
    #pragma unroll
    for (int j = 0; j < 5; ++j)
        breg[j] = *(const unsigned long long*)(Bs + cg*10 + 2*j);

    const float* atb = At + rg*4;
    const float* wb  = Ws + cg*10;

    // register carry of c(r0, prev col) -> c_top for cell1 (race-free)
    float c0prev[4] = {0.0f, 0.0f, 0.0f, 0.0f};

    for (int t = 0; t <= WW; ++t) {
        // ---- staging: x LDGs first ----
        float4 xv0, xv1;
        if (t < WW) {
            int c = flipW ? (WW-1-t) : t;
            xv0 = *(const float4*)(g_xT + (((size_t)(r0o*WW + c))*32 + sci)*32 + bh*16 + sb0);
        }
        if (t >= 1) {
            int c1 = t - 1;
            int c  = flipW ? (WW-1-c1) : c1;
            xv1 = *(const float4*)(g_xT + (((size_t)(r1o*WW + c))*32 + sci)*32 + bh*16 + sb0);
        }
        if (t < WW && p > 0) {
            if (tid == 0) { while ((int)ld_acq(upflag) < t + 1) { } }
            __syncthreads();
            size_t hb = (((size_t)(d*HH + r0 - 1))*WW + t)*CELLSZ + bh*512;
            float4 hv = *(const float4*)(g_hd + hb + sci*16 + sb0);
            float4 cv = *(const float4*)(g_cd + hb + sci*16 + sb0);
            *(float4*)(At + (64 + sci)*AT_P + sb0) = hv;   // h_top cell0
            Ct0[(sb0+0)*32 + sci] = cv.x;
            Ct0[(sb0+1)*32 + sci] = cv.y;
            Ct0[(sb0+2)*32 + sci] = cv.z;
            Ct0[(sb0+3)*32 + sci] = cv.w;
        }
        if (t < WW) *(float4*)(At + sci*AT_P + sb0)      = xv0;
        if (t >= 1) *(float4*)(At + sci*AT_P + 16 + sb0) = xv1;
        __syncthreads();

        // ---- GEMM: Z[32][160] = A[32][96] @ W[96][160] + bias ----
        {
            unsigned long long acc[4][5];
            #pragma unroll
            for (int r = 0; r < 4; ++r)
                #pragma unroll
                for (int j = 0; j < 5; ++j)
                    acc[r][j] = breg[j];

            #pragma unroll 2
            for (int k = 0; k < 96; ++k) {
                float4 av = *(const float4*)(atb + k*AT_P);
                unsigned long long wv[5];
                #pragma unroll
                for (int j = 0; j < 5; ++j)
                    wv[j] = *(const unsigned long long*)(wb + k*NG + 2*j);
                float as[4] = {av.x, av.y, av.z, av.w};
                #pragma unroll
                for (int r = 0; r < 4; ++r) {
                    unsigned long long aa;
                    asm("mov.b64 %0, {%1, %1};" : "=l"(aa) : "f"(as[r]));
                    #pragma unroll
                    for (int j = 0; j < 5; ++j)
                        asm("fma.rn.f32x2 %0, %1, %2, %0;" : "+l"(acc[r][j]) : "l"(wv[j]), "l"(aa));
                }
            }
            float* zb = Zs + (rg*4)*ZP + cg*10;
            #pragma unroll
            for (int r = 0; r < 4; ++r)
                #pragma unroll
                for (int j = 0; j < 5; ++j)
                    *(unsigned long long*)(zb + r*ZP + 2*j) = acc[r][j];
        }
        __syncthreads();

        // ---- gates: each thread owns (gch, bhat) for BOTH cells ----
        {
            const bool act0 = (t < WW);
            const bool act1 = (t >= 1);
            size_t base0 = (((size_t)(d*HH + r0))*WW + t)*CELLSZ + bh*512;
            size_t base1 = (((size_t)(d*HH + r1))*WW + (t-1))*CELLSZ + bh*512;
            #pragma unroll
            for (int j = 0; j < 4; ++j) {
                int bhat = bq + j;
                // cell1 FIRST: consumes c0prev from previous step (register)
                if (act1) {
                    int row = 16 + bhat;
                    const float* z = Zs + row*ZP + gch;
                    float cs = fsigmoid(z[32])*Cl[row*32 + gch]
                             + fsigmoid(z[64])*c0prev[j]
                             + fsigmoid(z[0])*ftanh(z[128]);
                    float h  = fsigmoid(z[96])*ftanh(cs);
                    Cl[row*32 + gch]              = cs;
                    At[(32+gch)*AT_P + 16 + bhat] = h;    // h_left(r1)
                    g_hd[base1 + gch*16 + bhat]   = h;    // boundary row
                    g_cd[base1 + gch*16 + bhat]   = cs;
                }
                // cell0: updates c0prev for next step
                if (act0) {
                    int row = bhat;
                    const float* z = Zs + row*ZP + gch;
                    float cs = fsigmoid(z[32])*Cl[row*32 + gch]
                             + fsigmoid(z[64])*Ct0[bhat*32 + gch]
                             + fsigmoid(z[0])*ftanh(z[128]);
                    float h  = fsigmoid(z[96])*ftanh(cs);
                    c0prev[j] = cs;                       // c_top cell1 next step
                    Cl[row*32 + gch]              = cs;
                    At[(32+gch)*AT_P + bhat]      = h;    // h_left(r0)
                    At[(64+gch)*AT_P + 16 + bhat] = h;    // h_top cell1 next step
                    g_hd[base0 + gch*16 + bhat]   = h;
                }
            }
        }
        __syncthreads();
        if (tid == 0 && t >= 1) {
            __threadfence();
            st_rel(myflag, (unsigned)t);
        }
    }
}

// ---------------- kernel 2: 4-dir sum + 2x2/2 conv + tanh + partial stats ----------------
__launch_bounds__(256, 2)
__global__ void conv_kernel(const float* __restrict__ conv_w, const float* __restrict__ conv_b) {
    extern __shared__ float sm2[];
    float* Hs = sm2;            // [rr][c][cl]  2*160*32
    float* Wt = sm2 + 10240;    // [cl*4+kh*2+kw][co] 128*64
    const int ho  = blockIdx.x;
    const int b   = blockIdx.y;
    const int tid = threadIdx.x;
    const int bsel = (b >> 4)*512 + (b & 15);   // bh*512 + bhat

    for (int i = tid; i < 128*64; i += 256) {
        int co = i & 63, q = i >> 6;
        Wt[i] = conv_w[co*128 + q];
    }
    for (int idx = tid; idx < 2*WW*32; idx += 256) {
        int cl = idx & 31;
        int c  = (idx >> 5) % WW;
        int rr = idx / (WW*32);
        int rg = 2*ho + rr;
        float v = 0.0f;
        #pragma unroll
        for (int d = 0; d < 4; ++d) {
            int Rd = (d >= 2) ? (HH-1-rg) : rg;
            int Cd = (d & 1)  ? (WW-1-c)  : c;
            v += g_hd[(((size_t)(d*HH + Rd))*WW + Cd)*CELLSZ + bsel + cl*16];
        }
        Hs[idx] = v;
    }
    __syncthreads();

    const int co = tid >> 2;
    const int ws = tid & 3;
    float acc[20];
    #pragma unroll
    for (int j = 0; j < 20; ++j) acc[j] = 0.0f;

    for (int cl = 0; cl < 32; ++cl) {
        float w00 = Wt[(cl*4+0)*64 + co];
        float w01 = Wt[(cl*4+1)*64 + co];
        float w10 = Wt[(cl*4+2)*64 + co];
        float w11 = Wt[(cl*4+3)*64 + co];
        #pragma unroll
        for (int j = 0; j < 20; ++j) {
            int wo = j*4 + ws;
            int c0 = 2*wo;
            acc[j] += Hs[c0*32 + cl]            * w00
                    + Hs[(c0+1)*32 + cl]        * w01
                    + Hs[(WW + c0)*32 + cl]     * w10
                    + Hs[(WW + c0 + 1)*32 + cl] * w11;
        }
    }

    float bb = 4.0f * conv_b[co];
    float s1 = 0.0f, s2 = 0.0f;
    float* ybase = g_y + (((size_t)b*CO_ + co)*HOo + ho)*WOo;
    #pragma unroll
    for (int j = 0; j < 20; ++j) {
        int wo = j*4 + ws;
        float y = ftanh(acc[j] + bb);
        ybase[wo] = y;
        s1 += y;
        s2 += y*y;
    }
    s1 += __shfl_down_sync(0xffffffffu, s1, 1, 4);
    s1 += __shfl_down_sync(0xffffffffu, s1, 2, 4);
    s2 += __shfl_down_sync(0xffffffffu, s2, 1, 4);
    s2 += __shfl_down_sync(0xffffffffu, s2, 2, 4);
    if (ws == 0) {
        int pp = b*HOo + ho;
        g_ps1[pp*CO_ + co] = s1;
        g_ps2[pp*CO_ + co] = s2;
    }
}

// ---------------- kernel 3: per-channel mean/var -> scale/shift ----------------
__global__ void reduce_kernel(const float* __restrict__ gamma, const float* __restrict__ beta) {
    __shared__ float sh1[256];
    __shared__ float sh2[256];
    const int co = blockIdx.x;
    const int t  = threadIdx.x;
    float s1 = 0.0f, s2 = 0.0f;
    for (int p = t; p < BB*HOo; p += 256) {
        s1 += g_ps1[p*CO_ + co];
        s2 += g_ps2[p*CO_ + co];
    }
    sh1[t] = s1; sh2[t] = s2;
    __syncthreads();
    for (int s = 128; s > 0; s >>= 1) {
        if (t < s) { sh1[t] += sh1[t+s]; sh2[t] += sh2[t+s]; }
        __syncthreads();
    }
    if (t == 0) {
        const float N = (float)(BB*HOo*WOo);
        float mean = sh1[0] / N;
        float var  = sh2[0] / N - mean*mean;
        float sc = gamma[co] * rsqrtf(var + 1e-5f);
        g_sc[co] = sc;
        g_sh[co] = beta[co] - mean*sc;
    }
}

// ---------------- kernel 4: normalize ----------------
__global__ void norm_kernel(float* __restrict__ out) {
    int t  = blockIdx.x * blockDim.x + threadIdx.x;
    int i0 = t * 4;
    int co = (i0 / (HOo*WOo)) & 63;
    float sc = g_sc[co], sh = g_sh[co];
    float4 v = *(const float4*)(g_y + i0);
    v.x = v.x*sc + sh;
    v.y = v.y*sc + sh;
    v.z = v.z*sc + sh;
    v.w = v.w*sc + sh;
    *(float4*)(out + i0) = v;
}

// ---------------- launcher ----------------
extern "C" void kernel_launch(void* const* d_in, const int* in_sizes, int n_in,
                              void* d_out, int out_size) {
    (void)in_sizes; (void)n_in; (void)out_size;
    const float* x      = (const float*)d_in[0];
    const float* Wx     = (const float*)d_in[1];
    const float* Ul     = (const float*)d_in[2];
    const float* Ut     = (const float*)d_in[3];
    const float* bias   = (const float*)d_in[4];
    const float* conv_w = (const float*)d_in[5];
    const float* conv_b = (const float*)d_in[6];
    const float* gamma  = (const float*)d_in[7];
    const float* beta   = (const float*)d_in[8];
    float* out = (float*)d_out;

    cudaFuncSetAttribute(mdlstm_kernel, cudaFuncAttributeMaxDynamicSharedMemorySize, SM_TOT*4);
    cudaFuncSetAttribute(conv_kernel,   cudaFuncAttributeMaxDynamicSharedMemorySize, (10240+8192)*4);

    prep_kernel<<<7680, 256>>>(x);
    // 3 noops: harness pre-launch + prep + 3 noops -> mdlstm is the captured launch
    noop_kernel<<<1, 32>>>();
    noop_kernel<<<1, 32>>>();
    noop_kernel<<<1, 32>>>();
    mdlstm_kernel<<<NCHAIN*NPAIR, 128, SM_TOT*4>>>(Wx, Ul, Ut, bias);
    conv_kernel<<<dim3(HOo, BB), 256, (10240+8192)*4>>>(conv_w, conv_b);
    reduce_kernel<<<CO_, 256>>>(gamma, beta);
    norm_kernel<<<3840, 256>>>(out);
}

// round 11
// speedup vs baseline: 1.0032x; 1.0032x over previous
#include <cuda_runtime.h>
#include <cstdint>

// ---------------- problem constants ----------------
#define HH   48
#define WW   160
#define BB   32
#define CIn  32
#define NG   160            // 5*CL
#define CO_  64
#define HOo  24
#define WOo  80
#define CELLSZ 1024         // B*CL per (row,col) cell
#define DIRSZ  (HH*WW*CELLSZ)
#define NPAIR 24            // HH/2
#define NCHAIN 8            // 4 dirs x 2 batch halves

// ---------------- device scratch (static: allocation-free) ----------------
__device__ float    g_xT[HH*WW*BB*CIn];      // [r][c][ci][b]  (k-major for staging)
__device__ float    g_hd[4*DIRSZ];           // [d][row][col][bh*512 + ch*16 + bhat]
__device__ float    g_cd[4*DIRSZ];           // same layout (boundary rows used)
__device__ unsigned g_prog[NCHAIN*NPAIR];    // per-(chain,pair) boundary progress
__device__ float    g_y [BB*CO_*HOo*WOo];    // pre-norm conv output
__device__ float    g_ps1[BB*HOo*CO_];
__device__ float    g_ps2[BB*HOo*CO_];
__device__ float    g_sc[CO_];
__device__ float    g_sh[CO_];

// ---------------- helpers ----------------
__device__ __forceinline__ unsigned ld_acq(const unsigned* p) {
    unsigned v;
    asm volatile("ld.acquire.gpu.global.u32 %0, [%1];" : "=r"(v) : "l"(p) : "memory");
    return v;
}
__device__ __forceinline__ void st_rel(unsigned* p, unsigned v) {
    asm volatile("st.release.gpu.global.u32 [%0], %1;" :: "l"(p), "r"(v) : "memory");
}
__device__ __forceinline__ float fsigmoid(float x) {
    float e = __expf(-x);
    return __fdividef(1.0f, 1.0f + e);
}
__device__ __forceinline__ float ftanh(float x) {
    float ax = fabsf(x);
    float e  = __expf(-2.0f * ax);          // in (0,1], never overflows
    float r  = __fdividef(1.0f - e, 1.0f + e);
    return copysignf(r, x);
}

// ---------------- kernel 0: transpose x (k-major) + reset progress ----------------
__global__ void prep_kernel(const float* __restrict__ x) {
    int t = blockIdx.x * blockDim.x + threadIdx.x;   // 7680*256 threads, 1 float4 each
    if (t < NCHAIN*NPAIR) g_prog[t] = 0;
    int i0 = t * 4;
    int b0 = i0 & 31;                 // batch (fastest)
    int ci = (i0 >> 5) & 31;
    int c  = (i0 >> 10) % WW;
    int r  = i0 / (WW * CELLSZ);
    const float* xp = x + (((size_t)(b0*CIn + ci))*HH + r)*WW + c;
    const size_t bs = (size_t)CIn*HH*WW;  // stride between batches
    float4 v;
    v.x = xp[0];
    v.y = xp[bs];
    v.z = xp[2*bs];
    v.w = xp[3*bs];
    *(float4*)(g_xT + i0) = v;
}

// noop kernels: shift ncu's capture window onto mdlstm_kernel
__global__ void noop_kernel() {}

// ---------------- kernel 1: 4-dir MDLSTM, paired rows, batch-split ----------------
// 192 CTAs x 128 threads; 2 CTAs co-resident per SM -> serial phases interleave.
// smem floats per CTA:
//   Ws[96*160]=15360 | Bs[160] | At[96*36]=3456 (k-major A: cols 0-15 cell0 bhat,
//   16-31 cell1 bhat) | Zs[32*164]=5248 | Cl[32*32] | Ct0[16*32]
#define AT_P 36
#define ZP   164
#define SM_WS  0
#define SM_BS  15360
#define SM_AT  15520
#define SM_ZS  18976
#define SM_CL  24224
#define SM_CT0 25248
#define SM_TOT 25760     // floats -> 103,040 bytes (x2 = 206 KB <= 227 KB)

__launch_bounds__(128)
__global__ void mdlstm_kernel(const float* __restrict__ Wx, const float* __restrict__ Ul,
                              const float* __restrict__ Ut, const float* __restrict__ bias) {
    extern __shared__ float sm[];
    float* Ws  = sm + SM_WS;    // [96][160]: k 0..31 Wx, 32..63 Ul, 64..95 Ut
    float* Bs  = sm + SM_BS;
    float* At  = sm + SM_AT;    // [96][36] k-major A panel
    float* Zs  = sm + SM_ZS;    // [32][164]
    float* Cl  = sm + SM_CL;    // c_left  [row32][ch32]
    float* Ct0 = sm + SM_CT0;   // c_top cell0 [bhat16][ch32]

    const int tid   = threadIdx.x;
    const int chain = blockIdx.x / NPAIR;      // d*2 + bh
    const int p     = blockIdx.x % NPAIR;
    const int d     = chain >> 1;
    const int bh    = chain & 1;
    const bool flipH = (d >= 2);
    const bool flipW = (d & 1);
    const int r0  = 2*p;
    const int r1  = 2*p + 1;
    const int r0o = flipH ? (HH-1-r0) : r0;
    const int r1o = flipH ? (HH-1-r1) : r1;

    for (int i = tid; i < 32*NG; i += 128) {
        Ws[i]         = Wx[d*32*NG + i];
        Ws[32*NG + i] = Ul[d*32*NG + i];
        Ws[64*NG + i] = Ut[d*32*NG + i];
    }
    for (int i = tid; i < NG; i += 128) Bs[i] = bias[d*NG + i];
    for (int i = tid; i < 96*AT_P; i += 128) At[i] = 0.0f;
    for (int i = tid; i < 1024; i += 128) {
        Cl[i] = 0.0f;
        if (i < 512) Ct0[i] = 0.0f;
    }
    __syncthreads();

    // GEMM map: 4 rows x 10 cols per thread
    const int rg = tid >> 4;             // 0..7  (rows rg*4 .. rg*4+3)
    const int cg = tid & 15;             // 10 contiguous output cols
    // gates map: channel gch, bhats bq..bq+3, BOTH cells handled by same thread
    const int gch = tid & 31;
    const int bq  = (tid >> 5) * 4;
    // staging map: 1 channel x 4 batches per thread (conflict-free STS.128)
    const int sci = tid & 31;
    const int sb0 = (tid >> 5) * 4;

    unsigned* myflag = &g_prog[chain*NPAIR + p];
    const unsigned* upflag = (p > 0) ? &g_prog[chain*NPAIR + p - 1] : 0;

    // bias slice in registers (f32x2 pairs)
    unsigned long long breg[5];
    #pragma unroll
    for (int j = 0; j < 5; ++j)
        breg[j] = *(const unsigned long long*)(Bs + cg*10 + 2*j);

    const float* atb = At + rg*4;
    const float* wb  = Ws + cg*10;

    // register carry of c(r0, prev col) -> c_top for cell1 (race-free)
    float c0prev[4] = {0.0f, 0.0f, 0.0f, 0.0f};

    for (int t = 0; t <= WW; ++t) {
        // ---- staging: x LDGs first ----
        float4 xv0, xv1;
        if (t < WW) {
            int c = flipW ? (WW-1-t) : t;
            xv0 = *(const float4*)(g_xT + (((size_t)(r0o*WW + c))*32 + sci)*32 + bh*16 + sb0);
        }
        if (t >= 1) {
            int c1 = t - 1;
            int c  = flipW ? (WW-1-c1) : c1;
            xv1 = *(const float4*)(g_xT + (((size_t)(r1o*WW + c))*32 + sci)*32 + bh*16 + sb0);
        }
        if (t < WW && p > 0) {
            if (tid == 0) { while ((int)ld_acq(upflag) < t + 1) { } }
            __syncthreads();
            size_t hb = (((size_t)(d*HH + r0 - 1))*WW + t)*CELLSZ + bh*512;
            float4 hv = *(const float4*)(g_hd + hb + sci*16 + sb0);
            float4 cv = *(const float4*)(g_cd + hb + sci*16 + sb0);
            *(float4*)(At + (64 + sci)*AT_P + sb0) = hv;   // h_top cell0
            Ct0[(sb0+0)*32 + sci] = cv.x;
            Ct0[(sb0+1)*32 + sci] = cv.y;
            Ct0[(sb0+2)*32 + sci] = cv.z;
            Ct0[(sb0+3)*32 + sci] = cv.w;
        }
        if (t < WW) *(float4*)(At + sci*AT_P + sb0)      = xv0;
        if (t >= 1) *(float4*)(At + sci*AT_P + 16 + sb0) = xv1;
        __syncthreads();

        // ---- GEMM: Z[32][160] = A[32][96] @ W[96][160] + bias ----
        {
            unsigned long long acc[4][5];
            #pragma unroll
            for (int r = 0; r < 4; ++r)
                #pragma unroll
                for (int j = 0; j < 5; ++j)
                    acc[r][j] = breg[j];

            #pragma unroll 2
            for (int k = 0; k < 96; ++k) {
                float4 av = *(const float4*)(atb + k*AT_P);
                unsigned long long wv[5];
                #pragma unroll
                for (int j = 0; j < 5; ++j)
                    wv[j] = *(const unsigned long long*)(wb + k*NG + 2*j);
                float as[4] = {av.x, av.y, av.z, av.w};
                #pragma unroll
                for (int r = 0; r < 4; ++r) {
                    unsigned long long aa;
                    asm("mov.b64 %0, {%1, %1};" : "=l"(aa) : "f"(as[r]));
                    #pragma unroll
                    for (int j = 0; j < 5; ++j)
                        asm("fma.rn.f32x2 %0, %1, %2, %0;" : "+l"(acc[r][j]) : "l"(wv[j]), "l"(aa));
                }
            }
            float* zb = Zs + (rg*4)*ZP + cg*10;
            #pragma unroll
            for (int r = 0; r < 4; ++r)
                #pragma unroll
                for (int j = 0; j < 5; ++j)
                    *(unsigned long long*)(zb + r*ZP + 2*j) = acc[r][j];
        }
        __syncthreads();

        // ---- gates: each thread owns (gch, bhat) for BOTH cells ----
        {
            const bool act0 = (t < WW);
            const bool act1 = (t >= 1);
            size_t base0 = (((size_t)(d*HH + r0))*WW + t)*CELLSZ + bh*512;
            size_t base1 = (((size_t)(d*HH + r1))*WW + (t-1))*CELLSZ + bh*512;
            #pragma unroll
            for (int j = 0; j < 4; ++j) {
                int bhat = bq + j;
                // cell1 FIRST: consumes c0prev from previous step (register)
                if (act1) {
                    int row = 16 + bhat;
                    const float* z = Zs + row*ZP + gch;
                    float cs = fsigmoid(z[32])*Cl[row*32 + gch]
                             + fsigmoid(z[64])*c0prev[j]
                             + fsigmoid(z[0])*ftanh(z[128]);
                    float h  = fsigmoid(z[96])*ftanh(cs);
                    Cl[row*32 + gch]              = cs;
                    At[(32+gch)*AT_P + 16 + bhat] = h;    // h_left(r1)
                    g_hd[base1 + gch*16 + bhat]   = h;    // boundary row
                    g_cd[base1 + gch*16 + bhat]   = cs;
                }
                // cell0: updates c0prev for next step
                if (act0) {
                    int row = bhat;
                    const float* z = Zs + row*ZP + gch;
                    float cs = fsigmoid(z[32])*Cl[row*32 + gch]
                             + fsigmoid(z[64])*Ct0[bhat*32 + gch]
                             + fsigmoid(z[0])*ftanh(z[128]);
                    float h  = fsigmoid(z[96])*ftanh(cs);
                    c0prev[j] = cs;                       // c_top cell1 next step
                    Cl[row*32 + gch]              = cs;
                    At[(32+gch)*AT_P + bhat]      = h;    // h_left(r0)
                    At[(64+gch)*AT_P + 16 + bhat] = h;    // h_top cell1 next step
                    g_hd[base0 + gch*16 + bhat]   = h;
                }
            }
        }
        __syncthreads();
        if (tid == 0 && t >= 1) {
            __threadfence();
            st_rel(myflag, (unsigned)t);
        }
    }
}

// ---------------- kernel 2: 4-dir sum + 2x2/2 conv + tanh + partial stats ----------------
__launch_bounds__(256, 2)
__global__ void conv_kernel(const float* __restrict__ conv_w, const float* __restrict__ conv_b) {
    extern __shared__ float sm2[];
    float* Hs = sm2;            // [rr][c][cl]  2*160*32
    float* Wt = sm2 + 10240;    // [cl*4+kh*2+kw][co] 128*64
    const int ho  = blockIdx.x;
    const int b   = blockIdx.y;
    const int tid = threadIdx.x;
    const int bsel = (b >> 4)*512 + (b & 15);   // bh*512 + bhat

    for (int i = tid; i < 128*64; i += 256) {
        int co = i & 63, q = i >> 6;
        Wt[i] = conv_w[co*128 + q];
    }
    for (int idx = tid; idx < 2*WW*32; idx += 256) {
        int cl = idx & 31;
        int c  = (idx >> 5) % WW;
        int rr = idx / (WW*32);
        int rg = 2*ho + rr;
        float v = 0.0f;
        #pragma unroll
        for (int d = 0; d < 4; ++d) {
            int Rd = (d >= 2) ? (HH-1-rg) : rg;
            int Cd = (d & 1)  ? (WW-1-c)  : c;
            v += g_hd[(((size_t)(d*HH + Rd))*WW + Cd)*CELLSZ + bsel + cl*16];
        }
        Hs[idx] = v;
    }
    __syncthreads();

    const int co = tid >> 2;
    const int ws = tid & 3;
    float acc[20];
    #pragma unroll
    for (int j = 0; j < 20; ++j) acc[j] = 0.0f;

    for (int cl = 0; cl < 32; ++cl) {
        float w00 = Wt[(cl*4+0)*64 + co];
        float w01 = Wt[(cl*4+1)*64 + co];
        float w10 = Wt[(cl*4+2)*64 + co];
        float w11 = Wt[(cl*4+3)*64 + co];
        #pragma unroll
        for (int j = 0; j < 20; ++j) {
            int wo = j*4 + ws;
            int c0 = 2*wo;
            acc[j] += Hs[c0*32 + cl]            * w00
                    + Hs[(c0+1)*32 + cl]        * w01
                    + Hs[(WW + c0)*32 + cl]     * w10
                    + Hs[(WW + c0 + 1)*32 + cl] * w11;
        }
    }

    float bb = 4.0f * conv_b[co];
    float s1 = 0.0f, s2 = 0.0f;
    float* ybase = g_y + (((size_t)b*CO_ + co)*HOo + ho)*WOo;
    #pragma unroll
    for (int j = 0; j < 20; ++j) {
        int wo = j*4 + ws;
        float y = ftanh(acc[j] + bb);
        ybase[wo] = y;
        s1 += y;
        s2 += y*y;
    }
    s1 += __shfl_down_sync(0xffffffffu, s1, 1, 4);
    s1 += __shfl_down_sync(0xffffffffu, s1, 2, 4);
    s2 += __shfl_down_sync(0xffffffffu, s2, 1, 4);
    s2 += __shfl_down_sync(0xffffffffu, s2, 2, 4);
    if (ws == 0) {
        int pp = b*HOo + ho;
        g_ps1[pp*CO_ + co] = s1;
        g_ps2[pp*CO_ + co] = s2;
    }
}

// ---------------- kernel 3: per-channel mean/var -> scale/shift ----------------
__global__ void reduce_kernel(const float* __restrict__ gamma, const float* __restrict__ beta) {
    __shared__ float sh1[256];
    __shared__ float sh2[256];
    const int co = blockIdx.x;
    const int t  = threadIdx.x;
    float s1 = 0.0f, s2 = 0.0f;
    for (int p = t; p < BB*HOo; p += 256) {
        s1 += g_ps1[p*CO_ + co];
        s2 += g_ps2[p*CO_ + co];
    }
    sh1[t] = s1; sh2[t] = s2;
    __syncthreads();
    for (int s = 128; s > 0; s >>= 1) {
        if (t < s) { sh1[t] += sh1[t+s]; sh2[t] += sh2[t+s]; }
        __syncthreads();
    }
    if (t == 0) {
        const float N = (float)(BB*HOo*WOo);
        float mean = sh1[0] / N;
        float var  = sh2[0] / N - mean*mean;
        float sc = gamma[co] * rsqrtf(var + 1e-5f);
        g_sc[co] = sc;
        g_sh[co] = beta[co] - mean*sc;
    }
}

// ---------------- kernel 4: normalize ----------------
__global__ void norm_kernel(float* __restrict__ out) {
    int t  = blockIdx.x * blockDim.x + threadIdx.x;
    int i0 = t * 4;
    int co = (i0 / (HOo*WOo)) & 63;
    float sc = g_sc[co], sh = g_sh[co];
    float4 v = *(const float4*)(g_y + i0);
    v.x = v.x*sc + sh;
    v.y = v.y*sc + sh;
    v.z = v.z*sc + sh;
    v.w = v.w*sc + sh;
    *(float4*)(out + i0) = v;
}

// ---------------- launcher ----------------
extern "C" void kernel_launch(void* const* d_in, const int* in_sizes, int n_in,
                              void* d_out, int out_size) {
    (void)in_sizes; (void)n_in; (void)out_size;
    const float* x      = (const float*)d_in[0];
    const float* Wx     = (const float*)d_in[1];
    const float* Ul     = (const float*)d_in[2];
    const float* Ut     = (const float*)d_in[3];
    const float* bias   = (const float*)d_in[4];
    const float* conv_w = (const float*)d_in[5];
    const float* conv_b = (const float*)d_in[6];
    const float* gamma  = (const float*)d_in[7];
    const float* beta   = (const float*)d_in[8];
    float* out = (float*)d_out;

    cudaFuncSetAttribute(mdlstm_kernel, cudaFuncAttributeMaxDynamicSharedMemorySize, SM_TOT*4);
    cudaFuncSetAttribute(conv_kernel,   cudaFuncAttributeMaxDynamicSharedMemorySize, (10240+8192)*4);

    prep_kernel<<<7680, 256>>>(x);
    // 3 noops: harness pre-launch + prep + 3 noops -> mdlstm is the captured launch
    noop_kernel<<<1, 32>>>();
    noop_kernel<<<1, 32>>>();
    noop_kernel<<<1, 32>>>();
    mdlstm_kernel<<<NCHAIN*NPAIR, 128, SM_TOT*4>>>(Wx, Ul, Ut, bias);
    conv_kernel<<<dim3(HOo, BB), 256, (10240+8192)*4>>>(conv_w, conv_b);
    reduce_kernel<<<CO_, 256>>>(gamma, beta);
    norm_kernel<<<3840, 256>>>(out);
}